// round 6
// baseline (speedup 1.0000x reference)
#include <cuda_runtime.h>
#include <math.h>

// Qwen2.5 MoE expert router, fused single kernel.
// Round 6: FFMA2 (fma.rn.f32x2) GEMM at 2 warps/SMSP, R3 tiling (BM=128, grid=128),
// fused last-block aux-loss reduction. Bit-exact fp32 per lane.
// out layout (fp32, reference return order):
//   [0, NE) dispatch | [NE, 2NE) combine | [2NE, 3NE) logits | [3NE, 4NE) probs
//   [4NE] aux_loss | [4NE+1, +2N) top_k_idx (as float) | next 2N: top_k_probs_norm

#define D_DIM 2048
#define E_DIM 64
#define BM 128
#define BK 32
#define NTHREADS 256
#define TN 4                 // experts per thread
#define KT (D_DIM / BK)      // 64 k-tiles
#define A_STRIDE (BM + 4)    // 132
#define B_STRIDE (E_DIM + 4) // 68
#define L_STRIDE (E_DIM + 1) // 65

#define A_ELEMS (BK * A_STRIDE)            // 4224
#define B_ELEMS (BK * B_STRIDE)            // 2176
#define L_ELEMS (BM * L_STRIDE)            // 8320
#define SPART_ELEMS (8 * E_DIM)            // 512
#define SMEM_ELEMS (L_ELEMS + SPART_ELEMS) // 8832 > A+B = 6400

typedef unsigned long long u64;

__device__ __forceinline__ u64 dup2(float v) {
    u64 r;
    asm("mov.b64 %0, {%1, %1};" : "=l"(r) : "f"(v));
    return r;
}
__device__ __forceinline__ void ffma2(u64& acc, u64 a, u64 b) {
    asm("fma.rn.f32x2 %0, %1, %2, %0;" : "+l"(acc) : "l"(a), "l"(b));
}
__device__ __forceinline__ void unpack2(u64 v, float& lo, float& hi) {
    asm("mov.b64 {%0, %1}, %2;" : "=f"(lo), "=f"(hi) : "l"(v));
}

__device__ float g_partials[128 * E_DIM];
__device__ unsigned int g_count = 0;

__global__ __launch_bounds__(NTHREADS)
void router_fused_kernel(const float* __restrict__ x,
                         const float* __restrict__ w,
                         float* __restrict__ out,
                         int N)
{
    __shared__ float smem[SMEM_ELEMS];
    __shared__ int sIsLast;
    float* As = smem;               // [BK][BM+4] transposed, GEMM phase
    float* Bs = smem + A_ELEMS;     // [BK][E+4]  transposed, GEMM phase
    float* Lg = smem;               // [BM][E+1]  epilogue (aliases As/Bs)
    float* sPart = smem + L_ELEMS;  // [8][E]

    const int tid = threadIdx.x;
    const int block_row = blockIdx.x * BM;

    // compute mapping: 16 expert groups x 16 token groups
    const int tc = tid & 15;
    const int tr = tid >> 4;
    const int e0 = tc * TN;        // 0..60
    const int m0 = tr * 8;         // 0..120 (8 tokens = 4 packed pairs)

    // staging mapping
    const int lk = (tid & 7) * 4;  // 0..28
    const int lr = tid >> 3;       // 0..31

    float4 aReg[4];
    float4 bReg[2];

    u64 acc[4][TN];                // 4 token-pairs x 4 experts
    #pragma unroll
    for (int i = 0; i < 4; i++)
        #pragma unroll
        for (int j = 0; j < TN; j++) acc[i][j] = 0ull;

    // ---- prologue ----
    #pragma unroll
    for (int p = 0; p < 4; p++) {
        int row = block_row + p * 32 + lr;
        aReg[p] = (row < N)
            ? *reinterpret_cast<const float4*>(x + (size_t)row * D_DIM + lk)
            : make_float4(0.f, 0.f, 0.f, 0.f);
    }
    #pragma unroll
    for (int p = 0; p < 2; p++) {
        int er = p * 32 + lr;
        bReg[p] = *reinterpret_cast<const float4*>(w + (size_t)er * D_DIM + lk);
    }

    for (int kt = 0; kt < KT; kt++) {
        __syncthreads();

        #pragma unroll
        for (int p = 0; p < 4; p++) {
            int m = p * 32 + lr;
            As[(lk + 0) * A_STRIDE + m] = aReg[p].x;
            As[(lk + 1) * A_STRIDE + m] = aReg[p].y;
            As[(lk + 2) * A_STRIDE + m] = aReg[p].z;
            As[(lk + 3) * A_STRIDE + m] = aReg[p].w;
        }
        #pragma unroll
        for (int p = 0; p < 2; p++) {
            int e = p * 32 + lr;
            Bs[(lk + 0) * B_STRIDE + e] = bReg[p].x;
            Bs[(lk + 1) * B_STRIDE + e] = bReg[p].y;
            Bs[(lk + 2) * B_STRIDE + e] = bReg[p].z;
            Bs[(lk + 3) * B_STRIDE + e] = bReg[p].w;
        }
        __syncthreads();

        if (kt + 1 < KT) {
            const int kbase = (kt + 1) * BK;
            #pragma unroll
            for (int p = 0; p < 4; p++) {
                int row = block_row + p * 32 + lr;
                aReg[p] = (row < N)
                    ? *reinterpret_cast<const float4*>(x + (size_t)row * D_DIM + kbase + lk)
                    : make_float4(0.f, 0.f, 0.f, 0.f);
            }
            #pragma unroll
            for (int p = 0; p < 2; p++) {
                int er = p * 32 + lr;
                bReg[p] = *reinterpret_cast<const float4*>(w + (size_t)er * D_DIM + kbase + lk);
            }
        }

        #pragma unroll 4
        for (int kk = 0; kk < BK; kk++) {
            // a token-pairs: 2x LDS.128 (16-lane broadcast, conflict-free)
            ulonglong2 a01 = *reinterpret_cast<const ulonglong2*>(&As[kk * A_STRIDE + m0]);
            ulonglong2 a23 = *reinterpret_cast<const ulonglong2*>(&As[kk * A_STRIDE + m0 + 4]);
            u64 ap[4] = {a01.x, a01.y, a23.x, a23.y};
            // b scalars: 1x LDS.128 (R3 pattern), duplicated into packed pairs
            float4 b = *reinterpret_cast<const float4*>(&Bs[kk * B_STRIDE + e0]);
            u64 bd[TN] = {dup2(b.x), dup2(b.y), dup2(b.z), dup2(b.w)};
            #pragma unroll
            for (int i = 0; i < 4; i++)
                #pragma unroll
                for (int j = 0; j < TN; j++)
                    ffma2(acc[i][j], ap[i], bd[j]);
        }
    }

    // ---- epilogue: logits -> smem ----
    __syncthreads();
    #pragma unroll
    for (int i = 0; i < 4; i++)
        #pragma unroll
        for (int j = 0; j < TN; j++) {
            float lo, hi;
            unpack2(acc[i][j], lo, hi);
            Lg[(m0 + 2 * i)     * L_STRIDE + (e0 + j)] = lo;
            Lg[(m0 + 2 * i + 1) * L_STRIDE + (e0 + j)] = hi;
        }
    __syncthreads();

    const int warpId = tid >> 5;   // 0..7
    const int lane = tid & 31;
    const size_t NE = (size_t)N * E_DIM;
    const float NEG_INF = __int_as_float(0xff800000);

    float auxA = 0.f, auxB = 0.f;

    for (int tk = warpId; tk < BM; tk += 8) {
        int n = block_row + tk;
        if (n >= N) continue;  // warp-uniform

        float v0 = Lg[tk * L_STRIDE + lane];
        float v1 = Lg[tk * L_STRIDE + lane + 32];

        float mx = fmaxf(v0, v1);
        #pragma unroll
        for (int o = 16; o; o >>= 1) mx = fmaxf(mx, __shfl_xor_sync(0xffffffffu, mx, o));
        float x0 = expf(v0 - mx), x1 = expf(v1 - mx);
        float s = x0 + x1;
        #pragma unroll
        for (int o = 16; o; o >>= 1) s += __shfl_xor_sync(0xffffffffu, s, o);
        float p0 = x0 / s, p1 = x1 / s;
        auxA += p0; auxB += p1;

        // top-1 (tie -> smallest index, matching jax.lax.top_k)
        float bvv; int bi;
        if (p0 >= p1) { bvv = p0; bi = lane; } else { bvv = p1; bi = lane + 32; }
        #pragma unroll
        for (int o = 16; o; o >>= 1) {
            float ov = __shfl_xor_sync(0xffffffffu, bvv, o);
            int   oi = __shfl_xor_sync(0xffffffffu, bi, o);
            if (ov > bvv || (ov == bvv && oi < bi)) { bvv = ov; bi = oi; }
        }
        // top-2
        float c0 = (lane == bi) ? NEG_INF : p0;
        float c1 = (lane + 32 == bi) ? NEG_INF : p1;
        float sv; int si;
        if (c0 >= c1) { sv = c0; si = lane; } else { sv = c1; si = lane + 32; }
        #pragma unroll
        for (int o = 16; o; o >>= 1) {
            float ov = __shfl_xor_sync(0xffffffffu, sv, o);
            int   oi = __shfl_xor_sync(0xffffffffu, si, o);
            if (ov > sv || (ov == sv && oi < si)) { sv = ov; si = oi; }
        }

        float tsum = bvv + sv;
        float pn1 = bvv / tsum, pn2 = sv / tsum;

        size_t rowL = (size_t)n * E_DIM;
        out[2 * NE + rowL + lane]      = v0;
        out[2 * NE + rowL + lane + 32] = v1;
        out[3 * NE + rowL + lane]      = p0;
        out[3 * NE + rowL + lane + 32] = p1;
        float d0 = (lane == bi) ? pn1 : ((lane == si) ? pn2 : 0.f);
        float d1 = (lane + 32 == bi) ? pn1 : ((lane + 32 == si) ? pn2 : 0.f);
        out[rowL + lane]           = d0;
        out[rowL + lane + 32]      = d1;
        out[NE + rowL + lane]      = d0;
        out[NE + rowL + lane + 32] = d1;
        if (lane == 0) {
            size_t o5 = 4 * NE + 1 + (size_t)n * 2;
            out[o5]     = (float)bi;
            out[o5 + 1] = (float)si;
            size_t o6 = 4 * NE + 1 + (size_t)N * 2 + (size_t)n * 2;
            out[o6]     = pn1;
            out[o6 + 1] = pn2;
        }
    }

    // per-block per-expert prob sums (deterministic fixed warp order)
    sPart[warpId * E_DIM + lane]      = auxA;
    sPart[warpId * E_DIM + lane + 32] = auxB;
    __syncthreads();
    if (tid < E_DIM) {
        float ssum = 0.f;
        #pragma unroll
        for (int wd = 0; wd < 8; wd++) ssum += sPart[wd * E_DIM + tid];
        g_partials[blockIdx.x * E_DIM + tid] = ssum;
    }
    __threadfence();
    if (tid == 0) {
        unsigned int prev = atomicAdd(&g_count, 1u);
        sIsLast = (prev == (unsigned int)(gridDim.x - 1)) ? 1 : 0;
    }
    __syncthreads();

    // ---- last block: deterministic aux-loss reduction ----
    if (sIsLast) {
        __threadfence();
        const int nBlocks = gridDim.x;
        int e = tid & 63;
        int q = tid >> 6;   // 0..3
        float s = 0.f;
        for (int b = q; b < nBlocks; b += 4) s += g_partials[b * E_DIM + e];
        sPart[q * E_DIM + e] = s;
        __syncthreads();
        if (tid < E_DIM) {
            float t = sPart[0 * E_DIM + tid] + sPart[1 * E_DIM + tid]
                    + sPart[2 * E_DIM + tid] + sPart[3 * E_DIM + tid];
            float m = t / (float)N;
            Lg[tid] = m * m;
        }
        __syncthreads();
        if (tid == 0) {
            float a = 0.f;
            #pragma unroll
            for (int i = 0; i < E_DIM; i++) a += Lg[i];
            out[4 * NE] = a;   // mean_e(E*p^2) = sum_e pbar^2
            g_count = 0;       // reset for next graph replay
        }
    }
}

extern "C" void kernel_launch(void* const* d_in, const int* in_sizes, int n_in,
                              void* d_out, int out_size)
{
    const float* x = (const float*)d_in[0];   // [N, 2048]
    const float* w = (const float*)d_in[1];   // [64, 2048]
    float* out = (float*)d_out;

    int N = in_sizes[0] / D_DIM;              // 16384
    int nBlocks = (N + BM - 1) / BM;          // 128

    router_fused_kernel<<<nBlocks, NTHREADS>>>(x, w, out, N);
}